// round 4
// baseline (speedup 1.0000x reference)
#include <cuda_runtime.h>

// ---------------------------------------------------------------------------
// Net_25469156065564: PCNN forward. tf32 mma.sync GEMMs, 3-stage cp.async
// pipeline (single barrier per K-chunk), relu+pool fused into conv1 epilogue.
// ---------------------------------------------------------------------------

#define BATCH 512
#define LEN   100
#define XROWS 104
#define XC    750

// K padded to multiples of 32 (zero weights in tail)
#define K1P  768
#define K3P  2272
#define K5P  3776
#define K2AP 320
#define K2BP 608

__device__ __align__(16) float g_Xpad[BATCH * XROWS * XC + 64];
__device__ __align__(16) float g_P [BATCH * 50 * 300 + 64];
__device__ __align__(16) float g_A2[BATCH * 52 * 200 + 64];
__device__ __align__(16) float g_O3[BATCH * 50 * 300];
__device__ __align__(16) float g_H [BATCH * 300];
// weight arrays padded to 128-row multiples (pad rows stay zero)
__device__ __align__(16) float g_W1 [128 * K1P];
__device__ __align__(16) float g_W3 [128 * K3P];
__device__ __align__(16) float g_W5 [128 * K5P];
__device__ __align__(16) float g_W2a[256 * K2AP];
__device__ __align__(16) float g_W2b[384 * K2BP];

__device__ __forceinline__ float f2tf_f(float f) {
    unsigned u;
    asm("cvt.rna.tf32.f32 %0, %1;" : "=r"(u) : "f"(f));
    return __uint_as_float(u);
}

// ---------------------------------------------------------------------------
__global__ void prep_weights(const float* __restrict__ w11,
                             const float* __restrict__ w13,
                             const float* __restrict__ w15,
                             const float* __restrict__ w2a,
                             const float* __restrict__ w2b)
{
    int which = blockIdx.y;
    int idx = blockIdx.x * 256 + threadIdx.x;
    if (which == 0) {                       // w11 (100,250,3,1) -> [100][768]
        if (idx >= 100 * K1P) return;
        int o = idx / K1P, k = idx % K1P;
        float v = 0.f;
        if (k < 750) { int h = k / 250, ci = k % 250; v = w11[o * 750 + ci * 3 + h]; }
        g_W1[idx] = f2tf_f(v);
    } else if (which == 1) {                // w13 (100,250,3,3) -> [100][2272]
        if (idx >= 100 * K3P) return;
        int o = idx / K3P, k = idx % K3P;
        float v = 0.f;
        if (k < 2250) {
            int kw = k / 750, r = k % 750, h = r / 250, ci = r % 250;
            v = w13[o * 2250 + ci * 9 + h * 3 + kw];
        }
        g_W3[idx] = f2tf_f(v);
    } else if (which == 2) {                // w15 (100,250,3,5) -> [100][3776]
        if (idx >= 100 * K5P) return;
        int o = idx / K5P, k = idx % K5P;
        float v = 0.f;
        if (k < 3750) {
            int kw = k / 750, r = k % 750, h = r / 250, ci = r % 250;
            v = w15[o * 3750 + ci * 15 + h * 5 + kw];
        }
        g_W5[idx] = f2tf_f(v);
    } else if (which == 3) {                // w2b (300,200,1,3) -> [300][608]
        if (idx >= 300 * K2BP) return;
        int o = idx / K2BP, k = idx % K2BP;
        float v = 0.f;
        if (k < 600) { int kw = k / 200, c2 = k % 200; v = w2b[o * 600 + c2 * 3 + kw]; }
        g_W2b[idx] = f2tf_f(v);
    } else {                                // w2a (200,300,1,1) -> [200][320]
        if (idx >= 200 * K2AP) return;
        int o = idx / K2AP, k = idx % K2AP;
        g_W2a[idx] = (k < 300) ? f2tf_f(w2a[o * 300 + k]) : 0.f;
    }
}

// ---------------------------------------------------------------------------
__global__ void build_x(const int* __restrict__ tok,
                        const int* __restrict__ p1m,
                        const int* __restrict__ p2m,
                        const float* __restrict__ sdp,
                        const float* __restrict__ wemb,
                        const float* __restrict__ p1e,
                        const float* __restrict__ p2e)
{
    int blk = blockIdx.x;
    int b = blk / LEN, l = blk % LEN;
    int t  = tok[b * LEN + l];
    int p1 = p1m[b * LEN + l];
    int p2 = p2m[b * LEN + l];
    float s = sdp[b * LEN + l];
    float* row = g_Xpad + ((long)(b * XROWS + l + 2)) * XC;
    int tid = threadIdx.x;
    if (tid < 250) {
        float w = wemb[(long)t * 250 + tid];
        row[tid] = f2tf_f(w);
        row[500 + tid] = f2tf_f(s * w);
    }
    if (tid < 125) {
        row[250 + tid] = f2tf_f(p1e[p1 * 125 + tid]);
        row[375 + tid] = f2tf_f(p2e[p2 * 125 + tid]);
    }
}

// ---------------------------------------------------------------------------
// tf32 GEMM: C[m,n] = bias[m] + sum_k W[m*Kp+k] * X[(n/LOUT)*sB+(n%LOUT)*sL+k]
// CTA 128x128, BK=32, 8 warps (4M x 2N), warp 32x64, mma.m16n8k8.tf32.
// 3-stage cp.async pipeline, ONE __syncthreads per chunk.
// fusePool: epilogue does relu + pairwise-n max + tf32 round, writes pooled.
// ---------------------------------------------------------------------------
#define STG  4608          // floats per A or B tile (128*36)
#define STAGEF 9216        // floats per stage (A+B)

template<int LOUT>
__global__ __launch_bounds__(256, 2)
void gemm_mma(const float* __restrict__ W, const float* __restrict__ bias,
              const float* __restrict__ X, float* __restrict__ out,
              int M, int Kp, long sB, int sL, long oB, int oL,
              int mOff, int doRelu, int cvtOut, int fusePool)
{
    extern __shared__ float sm[];   // [3][A 4608 | B 4608]

    int tid = threadIdx.x;
    int lane = tid & 31;
    int warp = tid >> 5;
    int wm = warp & 3;
    int wn = warp >> 2;
    int lr = lane >> 2;
    int lc = lane & 3;
    int mBase = blockIdx.y * 128;
    int nBase = blockIdx.x * 128;

    // A: 16B chunks. row = (tid>>3)+32i, k-offset (tid&7)*4
    int aj = tid & 7, ar = tid >> 3;
    int aOff[4];
    unsigned aDst[4];
#pragma unroll
    for (int i = 0; i < 4; i++) {
        int row = ar + 32 * i;
        aOff[i] = (mBase + row) * Kp + aj * 4;
        aDst[i] = (unsigned)__cvta_generic_to_shared(sm + row * 36 + aj * 4);
    }
    // B: 8B chunks. col = (tid>>4)+16i, k-offset (tid&15)*2
    int bj = tid & 15, br = tid >> 4;
    long bOff[8];
    unsigned bDst[8];
#pragma unroll
    for (int i = 0; i < 8; i++) {
        int col = br + 16 * i;
        int n = nBase + col;
        int bb = n / LOUT, ll = n % LOUT;
        bOff[i] = (long)bb * sB + (long)ll * sL + bj * 2;
        bDst[i] = (unsigned)__cvta_generic_to_shared(sm + STG + col * 36 + bj * 2);
    }

    float acc[2][8][4];
#pragma unroll
    for (int i = 0; i < 2; i++)
#pragma unroll
        for (int j = 0; j < 8; j++)
#pragma unroll
            for (int q = 0; q < 4; q++) acc[i][j][q] = 0.f;

    int nCh = Kp >> 5;
    const unsigned stageB = (unsigned)STAGEF * 4u;

#define LOAD_STAGE(stage, buf)                                                  \
    do {                                                                        \
        unsigned so_ = (unsigned)(buf) * stageB;                                \
        int ko_ = (stage) * 32;                                                 \
        _Pragma("unroll")                                                       \
        for (int i_ = 0; i_ < 4; i_++)                                          \
            asm volatile("cp.async.cg.shared.global [%0],[%1],16;"              \
                         :: "r"(aDst[i_] + so_), "l"(W + aOff[i_] + ko_));      \
        _Pragma("unroll")                                                       \
        for (int i_ = 0; i_ < 8; i_++)                                          \
            asm volatile("cp.async.ca.shared.global [%0],[%1],8;"               \
                         :: "r"(bDst[i_] + so_), "l"(X + bOff[i_] + ko_));      \
    } while (0)

    // prologue: stages 0,1
    LOAD_STAGE(0, 0);
    asm volatile("cp.async.commit_group;");
    if (nCh > 1) LOAD_STAGE(1, 1);
    asm volatile("cp.async.commit_group;");

    int rd = 0, wr = 2;
    for (int c = 0; c < nCh; c++) {
        asm volatile("cp.async.wait_group 1;");
        __syncthreads();

        if (c + 2 < nCh) LOAD_STAGE(c + 2, wr);
        asm volatile("cp.async.commit_group;");   // may be empty (tail)

        const float* As = sm + rd * STAGEF;
        const float* Bs = As + STG;
#pragma unroll
        for (int kk = 0; kk < 4; kk++) {
            int k0 = kk * 8;
            unsigned af[2][4];
#pragma unroll
            for (int mi = 0; mi < 2; mi++) {
                int rb = wm * 32 + mi * 16;
                af[mi][0] = __float_as_uint(As[(rb + lr) * 36 + k0 + lc]);
                af[mi][1] = __float_as_uint(As[(rb + 8 + lr) * 36 + k0 + lc]);
                af[mi][2] = __float_as_uint(As[(rb + lr) * 36 + k0 + 4 + lc]);
                af[mi][3] = __float_as_uint(As[(rb + 8 + lr) * 36 + k0 + 4 + lc]);
            }
#pragma unroll
            for (int ni = 0; ni < 8; ni++) {
                int nb = wn * 64 + ni * 8;
                unsigned b0 = __float_as_uint(Bs[(nb + lr) * 36 + k0 + lc]);
                unsigned b1 = __float_as_uint(Bs[(nb + lr) * 36 + k0 + 4 + lc]);
#pragma unroll
                for (int mi = 0; mi < 2; mi++) {
                    asm volatile(
                        "mma.sync.aligned.m16n8k8.row.col.f32.tf32.tf32.f32 "
                        "{%0,%1,%2,%3}, {%4,%5,%6,%7}, {%8,%9}, {%0,%1,%2,%3};"
                        : "+f"(acc[mi][ni][0]), "+f"(acc[mi][ni][1]),
                          "+f"(acc[mi][ni][2]), "+f"(acc[mi][ni][3])
                        : "r"(af[mi][0]), "r"(af[mi][1]),
                          "r"(af[mi][2]), "r"(af[mi][3]),
                          "r"(b0), "r"(b1));
                }
            }
        }
        rd = (rd == 2) ? 0 : rd + 1;
        wr = (wr == 2) ? 0 : wr + 1;
    }

    // ---------------- epilogue ----------------
#pragma unroll
    for (int mi = 0; mi < 2; mi++) {
        int r0 = mBase + wm * 32 + mi * 16 + lr;
        int r1 = r0 + 8;
        float bv0 = (r0 < M) ? bias[r0] : 0.f;
        float bv1 = (r1 < M) ? bias[r1] : 0.f;
        if (fusePool) {
            // pair (n, n+1) = (l even, l+1): relu + max + tf32, one write per row
#pragma unroll
            for (int ni = 0; ni < 8; ni++) {
                int cb = nBase + wn * 64 + ni * 8 + lc * 2;
                int b2 = cb / LOUT, l2 = cb % LOUT;
                long base = (long)b2 * oB + (long)(l2 >> 1) * oL + mOff;
                if (r0 < M) {
                    float v = fmaxf(fmaxf(acc[mi][ni][0], acc[mi][ni][1]) + bv0, 0.f);
                    out[base + r0] = f2tf_f(v);
                }
                if (r1 < M) {
                    float v = fmaxf(fmaxf(acc[mi][ni][2], acc[mi][ni][3]) + bv1, 0.f);
                    out[base + r1] = f2tf_f(v);
                }
            }
        } else {
#pragma unroll
            for (int ni = 0; ni < 8; ni++) {
                int cb = nBase + wn * 64 + ni * 8 + lc * 2;
#pragma unroll
                for (int cc = 0; cc < 2; cc++) {
                    int n = cb + cc;
                    int b2 = n / LOUT, l2 = n % LOUT;
                    long base = (long)b2 * oB + (long)l2 * oL + mOff;
                    if (r0 < M) {
                        float v = acc[mi][ni][cc] + bv0;
                        if (doRelu) v = fmaxf(v, 0.f);
                        if (cvtOut) v = f2tf_f(v);
                        out[base + r0] = v;
                    }
                    if (r1 < M) {
                        float v = acc[mi][ni][2 + cc] + bv1;
                        if (doRelu) v = fmaxf(v, 0.f);
                        if (cvtOut) v = f2tf_f(v);
                        out[base + r1] = v;
                    }
                }
            }
        }
    }
#undef LOAD_STAGE
}

// max over all 50 positions
__global__ void pool3()
{
    int b = blockIdx.x;
    for (int c = threadIdx.x; c < 300; c += blockDim.x) {
        const float* src = g_O3 + (long)b * 15000 + c;
        float mx = src[0];
        for (int p = 1; p < 50; p++) mx = fmaxf(mx, src[p * 300]);
        g_H[b * 300 + c] = mx;
    }
}

// FC chain: 300 -> 100 (relu) -> 50 (relu) -> 15  (exact fp32)
__global__ void fc_chain(const float* __restrict__ d1w, const float* __restrict__ d1b,
                         const float* __restrict__ d2w, const float* __restrict__ d2b,
                         const float* __restrict__ d3w, const float* __restrict__ d3b,
                         float* __restrict__ out)
{
    __shared__ float h0[300], h1[100], h2[50];
    int b = blockIdx.x, tid = threadIdx.x;
    for (int i = tid; i < 300; i += 128) h0[i] = g_H[b * 300 + i];
    __syncthreads();
    if (tid < 100) {
        float s = d1b[tid];
        for (int k = 0; k < 300; k++) s += h0[k] * d1w[k * 100 + tid];
        h1[tid] = fmaxf(s, 0.f);
    }
    __syncthreads();
    if (tid < 50) {
        float s = d2b[tid];
        for (int k = 0; k < 100; k++) s += h1[k] * d2w[k * 50 + tid];
        h2[tid] = fmaxf(s, 0.f);
    }
    __syncthreads();
    if (tid < 15) {
        float s = d3b[tid];
        for (int k = 0; k < 50; k++) s += h2[k] * d3w[k * 15 + tid];
        out[b * 15 + tid] = s;
    }
}

extern "C" void kernel_launch(void* const* d_in, const int* in_sizes, int n_in,
                              void* d_out, int out_size)
{
    const int*   tok  = (const int*)  d_in[0];
    const int*   p1m  = (const int*)  d_in[1];
    const int*   p2m  = (const int*)  d_in[2];
    const float* sdp  = (const float*)d_in[3];
    const float* wemb = (const float*)d_in[4];
    const float* p1e  = (const float*)d_in[5];
    const float* p2e  = (const float*)d_in[6];
    const float* w11  = (const float*)d_in[7];
    const float* b11  = (const float*)d_in[8];
    const float* w13  = (const float*)d_in[9];
    const float* b13  = (const float*)d_in[10];
    const float* w15  = (const float*)d_in[11];
    const float* b15  = (const float*)d_in[12];
    const float* w2a  = (const float*)d_in[13];
    const float* b2a  = (const float*)d_in[14];
    const float* w2b  = (const float*)d_in[15];
    const float* b2b  = (const float*)d_in[16];
    const float* d1w  = (const float*)d_in[17];
    const float* d1b  = (const float*)d_in[18];
    const float* d2w  = (const float*)d_in[19];
    const float* d2b  = (const float*)d_in[20];
    const float* d3w  = (const float*)d_in[21];
    const float* d3b  = (const float*)d_in[22];

    float *Xpad, *P, *A2, *O3, *W1, *W3, *W5, *W2a, *W2b;
    cudaGetSymbolAddress((void**)&Xpad, g_Xpad);
    cudaGetSymbolAddress((void**)&P,   g_P);
    cudaGetSymbolAddress((void**)&A2,  g_A2);
    cudaGetSymbolAddress((void**)&O3,  g_O3);
    cudaGetSymbolAddress((void**)&W1,  g_W1);
    cudaGetSymbolAddress((void**)&W3,  g_W3);
    cudaGetSymbolAddress((void**)&W5,  g_W5);
    cudaGetSymbolAddress((void**)&W2a, g_W2a);
    cudaGetSymbolAddress((void**)&W2b, g_W2b);

    const int SMEM = 3 * STAGEF * 4;   // 110592 B
    cudaFuncSetAttribute(gemm_mma<100>, cudaFuncAttributeMaxDynamicSharedMemorySize, SMEM);
    cudaFuncSetAttribute(gemm_mma<50>,  cudaFuncAttributeMaxDynamicSharedMemorySize, SMEM);

    prep_weights<<<dim3((377600 + 255) / 256, 5), 256>>>(w11, w13, w15, w2a, w2b);

    build_x<<<BATCH * LEN, 256>>>(tok, p1m, p2m, sdp, wemb, p1e, p2e);

    // conv1 + relu + pool(2) fused: writes P[b][p][300] (tf32-rounded)
    gemm_mma<100><<<dim3(400, 1), 256, SMEM>>>(W5, b15, Xpad, P,
                                               100, K5P, (long)XROWS * XC, XC,
                                               15000, 300, 200, 1, 1, 1);
    gemm_mma<100><<<dim3(400, 1), 256, SMEM>>>(W3, b13, Xpad + 750, P,
                                               100, K3P, (long)XROWS * XC, XC,
                                               15000, 300, 100, 1, 1, 1);
    gemm_mma<100><<<dim3(400, 1), 256, SMEM>>>(W1, b11, Xpad + 2 * 750, P,
                                               100, K1P, (long)XROWS * XC, XC,
                                               15000, 300, 0, 1, 1, 1);

    // conv2a (1x1): out tf32-rounded into padded A2 rows 1..50
    gemm_mma<50><<<dim3(200, 2), 256, SMEM>>>(W2a, b2a, P, A2 + 200,
                                              200, K2AP, 15000, 300,
                                              10400, 200, 0, 0, 1, 0);

    // conv2b (kw=3, pad=1)
    gemm_mma<50><<<dim3(200, 3), 256, SMEM>>>(W2b, b2b, A2, O3,
                                              300, K2BP, 10400, 200,
                                              15000, 300, 0, 1, 0, 0);

    pool3<<<BATCH, 256>>>();

    fc_chain<<<BATCH, 128>>>(d1w, d1b, d2w, d2b, d3w, d3b, (float*)d_out);
}

// round 5
// speedup vs baseline: 2.0157x; 2.0157x over previous
#include <cuda_runtime.h>
#include <cuda_fp16.h>

// ---------------------------------------------------------------------------
// Net_25469156065564: PCNN forward. fp16 mma.sync m16n8k16 GEMMs (fp32 accum),
// 2-stage cp.async pipeline (R3-proven structure), BK=64 halves,
// relu+maxpool(2) fused into conv1 epilogue. All GEMM operands fp16.
// ---------------------------------------------------------------------------

#define BATCH 512
#define LEN   100
#define XROWS 104
#define XC    752          // 750 data + 2 pad halves (16B-aligned row stride)

// K windows padded to multiples of 64 (zero weights in tail / pad slots)
#define K1P  768           // window 750(+2 pad)
#define K3P  2304          // 3*752 = 2256
#define K5P  3776          // 5*752 = 3760
#define K2AP 320           // 300 (P stride 304)
#define K2BP 640           // 600 (A2 stride 200)

#define PSTR 304           // P row stride (halves), 608B = 16B-aligned

__device__ __align__(16) __half g_Xpad[BATCH * XROWS * XC + 128];
__device__ __align__(16) __half g_P [BATCH * 50 * PSTR + 128];
__device__ __align__(16) __half g_A2[BATCH * 52 * 200 + 128];
__device__ __align__(16) float  g_O3[BATCH * 50 * 300];
__device__ __align__(16) float  g_H [BATCH * 300];
// weight arrays padded to 128-row multiples (pad rows stay zero)
__device__ __align__(16) __half g_W1 [128 * K1P];
__device__ __align__(16) __half g_W3 [128 * K3P];
__device__ __align__(16) __half g_W5 [128 * K5P];
__device__ __align__(16) __half g_W2a[256 * K2AP];
__device__ __align__(16) __half g_W2b[384 * K2BP];

// ---------------------------------------------------------------------------
// Weight re-layouts into fp16, window-K layout matching padded X strides.
// conv1 K index: kw*752 + h*250 + ci  (pad slots 750,751 per row = 0)
// ---------------------------------------------------------------------------
__global__ void prep_weights(const float* __restrict__ w11,
                             const float* __restrict__ w13,
                             const float* __restrict__ w15,
                             const float* __restrict__ w2a,
                             const float* __restrict__ w2b)
{
    int which = blockIdx.y;
    int idx = blockIdx.x * 256 + threadIdx.x;
    if (which == 0) {                       // w11 (100,250,3,1) -> [100][768]
        if (idx >= 100 * K1P) return;
        int o = idx / K1P, k = idx % K1P;
        float v = 0.f;
        if (k < 750) { int h = k / 250, ci = k % 250; v = w11[o * 750 + ci * 3 + h]; }
        g_W1[idx] = __float2half_rn(v);
    } else if (which == 1) {                // w13 (100,250,3,3) -> [100][2304]
        if (idx >= 100 * K3P) return;
        int o = idx / K3P, k = idx % K3P;
        float v = 0.f;
        if (k < 2256) {
            int kw = k / 752, r = k % 752;
            if (r < 750) { int h = r / 250, ci = r % 250; v = w13[o * 2250 + ci * 9 + h * 3 + kw]; }
        }
        g_W3[idx] = __float2half_rn(v);
    } else if (which == 2) {                // w15 (100,250,3,5) -> [100][3776]
        if (idx >= 100 * K5P) return;
        int o = idx / K5P, k = idx % K5P;
        float v = 0.f;
        if (k < 3760) {
            int kw = k / 752, r = k % 752;
            if (r < 750) { int h = r / 250, ci = r % 250; v = w15[o * 3750 + ci * 15 + h * 5 + kw]; }
        }
        g_W5[idx] = __float2half_rn(v);
    } else if (which == 3) {                // w2b (300,200,1,3) -> [300][640]
        if (idx >= 300 * K2BP) return;
        int o = idx / K2BP, k = idx % K2BP;
        float v = 0.f;
        if (k < 600) { int kw = k / 200, c2 = k % 200; v = w2b[o * 600 + c2 * 3 + kw]; }
        g_W2b[idx] = __float2half_rn(v);
    } else {                                // w2a (200,300,1,1) -> [200][320]
        if (idx >= 200 * K2AP) return;
        int o = idx / K2AP, k = idx % K2AP;
        g_W2a[idx] = __float2half_rn((k < 300) ? w2a[o * 300 + k] : 0.f);
    }
}

// ---------------------------------------------------------------------------
// Build Xpad rows 2..101 (rows 0,1,102,103 + per-row pad slots stay zero).
__global__ void build_x(const int* __restrict__ tok,
                        const int* __restrict__ p1m,
                        const int* __restrict__ p2m,
                        const float* __restrict__ sdp,
                        const float* __restrict__ wemb,
                        const float* __restrict__ p1e,
                        const float* __restrict__ p2e)
{
    int blk = blockIdx.x;
    int b = blk / LEN, l = blk % LEN;
    int t  = tok[b * LEN + l];
    int p1 = p1m[b * LEN + l];
    int p2 = p2m[b * LEN + l];
    float s = sdp[b * LEN + l];
    __half* row = g_Xpad + ((long)(b * XROWS + l + 2)) * XC;
    int tid = threadIdx.x;
    if (tid < 250) {
        float w = wemb[(long)t * 250 + tid];
        row[tid] = __float2half_rn(w);
        row[500 + tid] = __float2half_rn(s * w);
    }
    if (tid < 125) {
        row[250 + tid] = __float2half_rn(p1e[p1 * 125 + tid]);
        row[375 + tid] = __float2half_rn(p2e[p2 * 125 + tid]);
    }
}

// ---------------------------------------------------------------------------
// fp16 GEMM: C[m,n] = bias[m] + sum_k W[m*Kp+k] * X[(n/LOUT)*sB+(n%LOUT)*sL+k]
// CTA 128x128, BK=64 halves, 8 warps (4M x 2N), warp 32x64, mma.m16n8k16.
// 2-stage cp.async (16B .cg everywhere); smem tiles [row][k] stride 72 halves
// (conflict-free 4B fragment loads). fusePool: relu + pairwise-n max -> half.
// ---------------------------------------------------------------------------
#define TILEH 9216     // halves per A or B tile (128*72)
#define STAGEH 18432   // halves per stage (A+B)

template<int LOUT>
__global__ __launch_bounds__(256, 2)
void gemm_mma(const __half* __restrict__ W, const float* __restrict__ bias,
              const __half* __restrict__ X, void* __restrict__ outv,
              int M, int Kp, long sB, int sL, long oB, int oL,
              int mOff, int doRelu, int outHalf, int fusePool)
{
    extern __shared__ __half sm[];   // [2][A 9216 | B 9216]

    int tid = threadIdx.x;
    int lane = tid & 31;
    int warp = tid >> 5;
    int wm = warp & 3;
    int wn = warp >> 2;
    int lr = lane >> 2;
    int lc = lane & 3;
    int mBase = blockIdx.y * 128;
    int nBase = blockIdx.x * 128;

    // cp.async mapping: both tiles 128 rows x 64 halves, 16B chunks.
    // thread -> row (tid>>3)+32i, chunk offset (tid&7)*8 halves
    int cj = (tid & 7) * 8, cr = tid >> 3;
    int aOff[4];
    long bOff[4];
    unsigned aDst[4], bDst[4];
#pragma unroll
    for (int i = 0; i < 4; i++) {
        int row = cr + 32 * i;
        aOff[i] = (mBase + row) * Kp + cj;
        aDst[i] = (unsigned)__cvta_generic_to_shared(sm + row * 72 + cj);
        int n = nBase + row;
        int bb = n / LOUT, ll = n % LOUT;
        bOff[i] = (long)bb * sB + (long)ll * sL + cj;
        bDst[i] = (unsigned)__cvta_generic_to_shared(sm + TILEH + row * 72 + cj);
    }

    float acc[2][8][4];
#pragma unroll
    for (int i = 0; i < 2; i++)
#pragma unroll
        for (int j = 0; j < 8; j++)
#pragma unroll
            for (int q = 0; q < 4; q++) acc[i][j][q] = 0.f;

    int nCh = Kp >> 6;
    const unsigned stageB = (unsigned)STAGEH * 2u;

#define LOAD_STAGE(ko_, so_)                                                    \
    do {                                                                        \
        _Pragma("unroll")                                                       \
        for (int i_ = 0; i_ < 4; i_++) {                                        \
            asm volatile("cp.async.cg.shared.global [%0],[%1],16;"              \
                         :: "r"(aDst[i_] + (so_)), "l"(W + aOff[i_] + (ko_)));  \
            asm volatile("cp.async.cg.shared.global [%0],[%1],16;"              \
                         :: "r"(bDst[i_] + (so_)), "l"(X + bOff[i_] + (ko_)));  \
        }                                                                       \
    } while (0)

    // prologue: stage 0
    LOAD_STAGE(0, 0u);
    asm volatile("cp.async.commit_group;");

    for (int c = 0; c < nCh; c++) {
        if (c + 1 < nCh) {
            LOAD_STAGE((c + 1) * 64, ((c + 1) & 1) ? stageB : 0u);
            asm volatile("cp.async.commit_group;");
            asm volatile("cp.async.wait_group 1;");
        } else {
            asm volatile("cp.async.wait_group 0;");
        }
        __syncthreads();

        const __half* As = sm + (c & 1) * STAGEH;
        const __half* Bs = As + TILEH;
#pragma unroll
        for (int kk = 0; kk < 4; kk++) {
            int k0 = kk * 16;
            unsigned af[2][4];
#pragma unroll
            for (int mi = 0; mi < 2; mi++) {
                int rb = wm * 32 + mi * 16;
                af[mi][0] = *(const unsigned*)(As + (rb + lr) * 72 + k0 + 2 * lc);
                af[mi][1] = *(const unsigned*)(As + (rb + 8 + lr) * 72 + k0 + 2 * lc);
                af[mi][2] = *(const unsigned*)(As + (rb + lr) * 72 + k0 + 8 + 2 * lc);
                af[mi][3] = *(const unsigned*)(As + (rb + 8 + lr) * 72 + k0 + 8 + 2 * lc);
            }
#pragma unroll
            for (int ni = 0; ni < 8; ni++) {
                int nb = wn * 64 + ni * 8;
                unsigned b0 = *(const unsigned*)(Bs + (nb + lr) * 72 + k0 + 2 * lc);
                unsigned b1 = *(const unsigned*)(Bs + (nb + lr) * 72 + k0 + 8 + 2 * lc);
#pragma unroll
                for (int mi = 0; mi < 2; mi++) {
                    asm volatile(
                        "mma.sync.aligned.m16n8k16.row.col.f32.f16.f16.f32 "
                        "{%0,%1,%2,%3}, {%4,%5,%6,%7}, {%8,%9}, {%0,%1,%2,%3};"
                        : "+f"(acc[mi][ni][0]), "+f"(acc[mi][ni][1]),
                          "+f"(acc[mi][ni][2]), "+f"(acc[mi][ni][3])
                        : "r"(af[mi][0]), "r"(af[mi][1]),
                          "r"(af[mi][2]), "r"(af[mi][3]),
                          "r"(b0), "r"(b1));
                }
            }
        }
        __syncthreads();
    }

    // ---------------- epilogue ----------------
#pragma unroll
    for (int mi = 0; mi < 2; mi++) {
        int r0 = mBase + wm * 32 + mi * 16 + lr;
        int r1 = r0 + 8;
        float bv0 = (r0 < M) ? bias[r0] : 0.f;
        float bv1 = (r1 < M) ? bias[r1] : 0.f;
        if (fusePool) {
            __half* o = (__half*)outv;
#pragma unroll
            for (int ni = 0; ni < 8; ni++) {
                int cb = nBase + wn * 64 + ni * 8 + lc * 2;
                int b2 = cb / LOUT, l2 = cb % LOUT;
                long base = (long)b2 * oB + (long)(l2 >> 1) * oL + mOff;
                if (r0 < M)
                    o[base + r0] = __float2half_rn(
                        fmaxf(fmaxf(acc[mi][ni][0], acc[mi][ni][1]) + bv0, 0.f));
                if (r1 < M)
                    o[base + r1] = __float2half_rn(
                        fmaxf(fmaxf(acc[mi][ni][2], acc[mi][ni][3]) + bv1, 0.f));
            }
        } else {
#pragma unroll
            for (int ni = 0; ni < 8; ni++) {
                int cb = nBase + wn * 64 + ni * 8 + lc * 2;
#pragma unroll
                for (int cc = 0; cc < 2; cc++) {
                    int n = cb + cc;
                    int b2 = n / LOUT, l2 = n % LOUT;
                    long base = (long)b2 * oB + (long)l2 * oL + mOff;
                    float v0 = acc[mi][ni][cc] + bv0;
                    float v1 = acc[mi][ni][2 + cc] + bv1;
                    if (doRelu) { v0 = fmaxf(v0, 0.f); v1 = fmaxf(v1, 0.f); }
                    if (outHalf) {
                        __half* o = (__half*)outv;
                        if (r0 < M) o[base + r0] = __float2half_rn(v0);
                        if (r1 < M) o[base + r1] = __float2half_rn(v1);
                    } else {
                        float* o = (float*)outv;
                        if (r0 < M) o[base + r0] = v0;
                        if (r1 < M) o[base + r1] = v1;
                    }
                }
            }
        }
    }
#undef LOAD_STAGE
}

// max over all 50 positions
__global__ void pool3()
{
    int b = blockIdx.x;
    for (int c = threadIdx.x; c < 300; c += blockDim.x) {
        const float* src = g_O3 + (long)b * 15000 + c;
        float mx = src[0];
        for (int p = 1; p < 50; p++) mx = fmaxf(mx, src[p * 300]);
        g_H[b * 300 + c] = mx;
    }
}

// FC chain: 300 -> 100 (relu) -> 50 (relu) -> 15  (exact fp32)
__global__ void fc_chain(const float* __restrict__ d1w, const float* __restrict__ d1b,
                         const float* __restrict__ d2w, const float* __restrict__ d2b,
                         const float* __restrict__ d3w, const float* __restrict__ d3b,
                         float* __restrict__ out)
{
    __shared__ float h0[300], h1[100], h2[50];
    int b = blockIdx.x, tid = threadIdx.x;
    for (int i = tid; i < 300; i += 128) h0[i] = g_H[b * 300 + i];
    __syncthreads();
    if (tid < 100) {
        float s = d1b[tid];
        for (int k = 0; k < 300; k++) s += h0[k] * d1w[k * 100 + tid];
        h1[tid] = fmaxf(s, 0.f);
    }
    __syncthreads();
    if (tid < 50) {
        float s = d2b[tid];
        for (int k = 0; k < 100; k++) s += h1[k] * d2w[k * 50 + tid];
        h2[tid] = fmaxf(s, 0.f);
    }
    __syncthreads();
    if (tid < 15) {
        float s = d3b[tid];
        for (int k = 0; k < 50; k++) s += h2[k] * d3w[k * 15 + tid];
        out[b * 15 + tid] = s;
    }
}

extern "C" void kernel_launch(void* const* d_in, const int* in_sizes, int n_in,
                              void* d_out, int out_size)
{
    const int*   tok  = (const int*)  d_in[0];
    const int*   p1m  = (const int*)  d_in[1];
    const int*   p2m  = (const int*)  d_in[2];
    const float* sdp  = (const float*)d_in[3];
    const float* wemb = (const float*)d_in[4];
    const float* p1e  = (const float*)d_in[5];
    const float* p2e  = (const float*)d_in[6];
    const float* w11  = (const float*)d_in[7];
    const float* b11  = (const float*)d_in[8];
    const float* w13  = (const float*)d_in[9];
    const float* b13  = (const float*)d_in[10];
    const float* w15  = (const float*)d_in[11];
    const float* b15  = (const float*)d_in[12];
    const float* w2a  = (const float*)d_in[13];
    const float* b2a  = (const float*)d_in[14];
    const float* w2b  = (const float*)d_in[15];
    const float* b2b  = (const float*)d_in[16];
    const float* d1w  = (const float*)d_in[17];
    const float* d1b  = (const float*)d_in[18];
    const float* d2w  = (const float*)d_in[19];
    const float* d2b  = (const float*)d_in[20];
    const float* d3w  = (const float*)d_in[21];
    const float* d3b  = (const float*)d_in[22];

    __half *Xpad, *P, *A2, *W1, *W3, *W5, *W2a, *W2b;
    float *O3;
    cudaGetSymbolAddress((void**)&Xpad, g_Xpad);
    cudaGetSymbolAddress((void**)&P,   g_P);
    cudaGetSymbolAddress((void**)&A2,  g_A2);
    cudaGetSymbolAddress((void**)&O3,  g_O3);
    cudaGetSymbolAddress((void**)&W1,  g_W1);
    cudaGetSymbolAddress((void**)&W3,  g_W3);
    cudaGetSymbolAddress((void**)&W5,  g_W5);
    cudaGetSymbolAddress((void**)&W2a, g_W2a);
    cudaGetSymbolAddress((void**)&W2b, g_W2b);

    const int SMEM = 2 * STAGEH * 2;   // 73728 B
    cudaFuncSetAttribute(gemm_mma<100>, cudaFuncAttributeMaxDynamicSharedMemorySize, SMEM);
    cudaFuncSetAttribute(gemm_mma<50>,  cudaFuncAttributeMaxDynamicSharedMemorySize, SMEM);

    prep_weights<<<dim3((100 * K5P + 255) / 256, 5), 256>>>(w11, w13, w15, w2a, w2b);

    build_x<<<BATCH * LEN, 256>>>(tok, p1m, p2m, sdp, wemb, p1e, p2e);

    // conv1 + relu + pool(2) fused -> P[b][p][PSTR] half
    gemm_mma<100><<<dim3(400, 1), 256, SMEM>>>(W5, b15, Xpad, P,
                                               100, K5P, (long)XROWS * XC, XC,
                                               50L * PSTR, PSTR, 200, 1, 1, 1);
    gemm_mma<100><<<dim3(400, 1), 256, SMEM>>>(W3, b13, Xpad + XC, P,
                                               100, K3P, (long)XROWS * XC, XC,
                                               50L * PSTR, PSTR, 100, 1, 1, 1);
    gemm_mma<100><<<dim3(400, 1), 256, SMEM>>>(W1, b11, Xpad + 2 * XC, P,
                                               100, K1P, (long)XROWS * XC, XC,
                                               50L * PSTR, PSTR, 0, 1, 1, 1);

    // conv2a (1x1) -> A2 half, padded rows 0,51 stay zero
    gemm_mma<50><<<dim3(200, 2), 256, SMEM>>>(W2a, b2a, P, A2 + 200,
                                              200, K2AP, 50L * PSTR, PSTR,
                                              10400, 200, 0, 0, 1, 0);

    // conv2b (kw=3, pad=1) + relu -> O3 float
    gemm_mma<50><<<dim3(200, 3), 256, SMEM>>>(W2b, b2b, A2, O3,
                                              300, K2BP, 10400, 200,
                                              15000, 300, 0, 1, 0, 0);

    pool3<<<BATCH, 256>>>();

    fc_chain<<<BATCH, 128>>>(d1w, d1b, d2w, d2b, d3w, d3b, (float*)d_out);
}

// round 6
// speedup vs baseline: 2.4185x; 1.1998x over previous
#include <cuda_runtime.h>
#include <cuda_fp16.h>

// ---------------------------------------------------------------------------
// Net_25469156065564: PCNN forward. fp16 mma.sync m16n8k16 (fp32 accum),
// ldmatrix fragment feed, 2-stage cp.async, conv1 trio fused in one launch,
// relu+maxpool(2) fused into conv1 epilogue.
// ---------------------------------------------------------------------------

#define BATCH 512
#define LEN   100
#define XROWS 104
#define XC    752          // 750 data + 2 pad halves (16B row stride)

#define K1P  768
#define K3P  2304          // 3*752=2256 -> 2304
#define K5P  3776          // 5*752=3760 -> 3776
#define K2AP 320
#define K2BP 640

#define PSTR 304           // P row stride (halves)

__device__ __align__(16) __half g_Xpad[BATCH * XROWS * XC + 128];
__device__ __align__(16) __half g_P [BATCH * 50 * PSTR + 128];
__device__ __align__(16) __half g_A2[BATCH * 52 * 200 + 128];
__device__ __align__(16) float  g_O3[BATCH * 50 * 300];
__device__ __align__(16) float  g_H [BATCH * 300];
__device__ __align__(16) __half g_W1 [128 * K1P];
__device__ __align__(16) __half g_W3 [128 * K3P];
__device__ __align__(16) __half g_W5 [128 * K5P];
__device__ __align__(16) __half g_W2a[256 * K2AP];
__device__ __align__(16) __half g_W2b[384 * K2BP];

// ---------------------------------------------------------------------------
__global__ void prep_weights(const float* __restrict__ w11,
                             const float* __restrict__ w13,
                             const float* __restrict__ w15,
                             const float* __restrict__ w2a,
                             const float* __restrict__ w2b)
{
    int which = blockIdx.y;
    int idx = blockIdx.x * 256 + threadIdx.x;
    if (which == 0) {                       // w11 (100,250,3,1) -> [100][768]
        if (idx >= 100 * K1P) return;
        int o = idx / K1P, k = idx % K1P;
        float v = 0.f;
        if (k < 750) { int h = k / 250, ci = k % 250; v = w11[o * 750 + ci * 3 + h]; }
        g_W1[idx] = __float2half_rn(v);
    } else if (which == 1) {                // w13 (100,250,3,3) -> [100][2304]
        if (idx >= 100 * K3P) return;
        int o = idx / K3P, k = idx % K3P;
        float v = 0.f;
        if (k < 2256) {
            int kw = k / 752, r = k % 752;
            if (r < 750) { int h = r / 250, ci = r % 250; v = w13[o * 2250 + ci * 9 + h * 3 + kw]; }
        }
        g_W3[idx] = __float2half_rn(v);
    } else if (which == 2) {                // w15 (100,250,3,5) -> [100][3776]
        if (idx >= 100 * K5P) return;
        int o = idx / K5P, k = idx % K5P;
        float v = 0.f;
        if (k < 3760) {
            int kw = k / 752, r = k % 752;
            if (r < 750) { int h = r / 250, ci = r % 250; v = w15[o * 3750 + ci * 15 + h * 5 + kw]; }
        }
        g_W5[idx] = __float2half_rn(v);
    } else if (which == 3) {                // w2b (300,200,1,3) -> [300][640]
        if (idx >= 300 * K2BP) return;
        int o = idx / K2BP, k = idx % K2BP;
        float v = 0.f;
        if (k < 600) { int kw = k / 200, c2 = k % 200; v = w2b[o * 600 + c2 * 3 + kw]; }
        g_W2b[idx] = __float2half_rn(v);
    } else {                                // w2a (200,300,1,1) -> [200][320]
        if (idx >= 200 * K2AP) return;
        int o = idx / K2AP, k = idx % K2AP;
        g_W2a[idx] = __float2half_rn((k < 300) ? w2a[o * 300 + k] : 0.f);
    }
}

// ---------------------------------------------------------------------------
__global__ void build_x(const int* __restrict__ tok,
                        const int* __restrict__ p1m,
                        const int* __restrict__ p2m,
                        const float* __restrict__ sdp,
                        const float* __restrict__ wemb,
                        const float* __restrict__ p1e,
                        const float* __restrict__ p2e)
{
    int blk = blockIdx.x;
    int b = blk / LEN, l = blk % LEN;
    int t  = tok[b * LEN + l];
    int p1 = p1m[b * LEN + l];
    int p2 = p2m[b * LEN + l];
    float s = sdp[b * LEN + l];
    __half* row = g_Xpad + ((long)(b * XROWS + l + 2)) * XC;
    int tid = threadIdx.x;
    if (tid < 250) {
        float w = wemb[(long)t * 250 + tid];
        row[tid] = __float2half_rn(w);
        row[500 + tid] = __float2half_rn(s * w);
    }
    if (tid < 125) {
        row[250 + tid] = __float2half_rn(p1e[p1 * 125 + tid]);
        row[375 + tid] = __float2half_rn(p2e[p2 * 125 + tid]);
    }
}

// ---------------------------------------------------------------------------
// GEMM body. CTA 128x128, BK=64 halves, 8 warps (4M x 2N), warp 32x64.
// ldmatrix fragment loads, mma.m16n8k16.f32.f16.
// ---------------------------------------------------------------------------
#define TILEH 9216     // halves per A or B tile (128*72)
#define STAGEH 18432   // halves per stage (A+B)

struct GArgs {
    const __half* W; const float* bias; const __half* X; void* out;
    int M, Kp; long sB; int sL; long oB; int oL;
    int mOff, doRelu, outHalf, fusePool;
};

template<int LOUT>
__device__ __forceinline__ void gemm_body(const GArgs g, int mBase, int nBase,
                                          __half* sm)
{
    const __half* __restrict__ W = g.W;
    const __half* __restrict__ X = g.X;

    int tid = threadIdx.x;
    int lane = tid & 31;
    int warp = tid >> 5;
    int wm = warp & 3;
    int wn = warp >> 2;
    int lr = lane >> 2;
    int lc = lane & 3;

    // cp.async mapping: both tiles 128 rows x 64 halves, 16B chunks.
    int cj = (tid & 7) * 8, cr = tid >> 3;
    int aOff[4];
    long bOff[4];
    unsigned aDst[4], bDst[4];
#pragma unroll
    for (int i = 0; i < 4; i++) {
        int row = cr + 32 * i;
        aOff[i] = (mBase + row) * g.Kp + cj;
        aDst[i] = (unsigned)__cvta_generic_to_shared(sm + row * 72 + cj);
        int n = nBase + row;
        int bb = n / LOUT, ll = n % LOUT;
        bOff[i] = (long)bb * g.sB + (long)ll * g.sL + cj;
        bDst[i] = (unsigned)__cvta_generic_to_shared(sm + TILEH + row * 72 + cj);
    }

    // ldmatrix base addresses (stage 0, k0 = 0)
    unsigned aLm[2], bLm[4];
    {
        int arow = (lane & 15);
        int akhi = (lane >> 4) * 8;
#pragma unroll
        for (int mi = 0; mi < 2; mi++) {
            int row = wm * 32 + mi * 16 + arow;
            aLm[mi] = (unsigned)__cvta_generic_to_shared(sm + row * 72 + akhi);
        }
        int bcol = ((lane >> 4) << 3) + (lane & 7);
        int bkhi = ((lane >> 3) & 1) * 8;
#pragma unroll
        for (int ni2 = 0; ni2 < 4; ni2++) {
            int col = wn * 64 + ni2 * 16 + bcol;
            bLm[ni2] = (unsigned)__cvta_generic_to_shared(sm + TILEH + col * 72 + bkhi);
        }
    }

    float acc[2][8][4];
#pragma unroll
    for (int i = 0; i < 2; i++)
#pragma unroll
        for (int j = 0; j < 8; j++)
#pragma unroll
            for (int q = 0; q < 4; q++) acc[i][j][q] = 0.f;

    int nCh = g.Kp >> 6;
    const unsigned stageB = (unsigned)STAGEH * 2u;

#define LOAD_STAGE(ko_, so_)                                                    \
    do {                                                                        \
        _Pragma("unroll")                                                       \
        for (int i_ = 0; i_ < 4; i_++) {                                        \
            asm volatile("cp.async.cg.shared.global [%0],[%1],16;"              \
                         :: "r"(aDst[i_] + (so_)), "l"(W + aOff[i_] + (ko_)));  \
            asm volatile("cp.async.cg.shared.global [%0],[%1],16;"              \
                         :: "r"(bDst[i_] + (so_)), "l"(X + bOff[i_] + (ko_)));  \
        }                                                                       \
    } while (0)

    LOAD_STAGE(0, 0u);
    asm volatile("cp.async.commit_group;");

    for (int c = 0; c < nCh; c++) {
        if (c + 1 < nCh) {
            LOAD_STAGE((c + 1) * 64, ((c + 1) & 1) ? stageB : 0u);
            asm volatile("cp.async.commit_group;");
            asm volatile("cp.async.wait_group 1;");
        } else {
            asm volatile("cp.async.wait_group 0;");
        }
        __syncthreads();

        unsigned so = (c & 1) ? stageB : 0u;
#pragma unroll
        for (int kk = 0; kk < 4; kk++) {
            unsigned ko = so + kk * 32;   // 16 halves = 32 bytes
            unsigned af[2][4];
#pragma unroll
            for (int mi = 0; mi < 2; mi++)
                asm volatile("ldmatrix.sync.aligned.m8n8.x4.shared.b16 "
                             "{%0,%1,%2,%3}, [%4];"
                             : "=r"(af[mi][0]), "=r"(af[mi][1]),
                               "=r"(af[mi][2]), "=r"(af[mi][3])
                             : "r"(aLm[mi] + ko));
#pragma unroll
            for (int ni2 = 0; ni2 < 4; ni2++) {
                unsigned b00, b01, b10, b11;
                asm volatile("ldmatrix.sync.aligned.m8n8.x4.shared.b16 "
                             "{%0,%1,%2,%3}, [%4];"
                             : "=r"(b00), "=r"(b01), "=r"(b10), "=r"(b11)
                             : "r"(bLm[ni2] + ko));
#pragma unroll
                for (int mi = 0; mi < 2; mi++) {
                    asm volatile(
                        "mma.sync.aligned.m16n8k16.row.col.f32.f16.f16.f32 "
                        "{%0,%1,%2,%3}, {%4,%5,%6,%7}, {%8,%9}, {%0,%1,%2,%3};"
                        : "+f"(acc[mi][2 * ni2][0]), "+f"(acc[mi][2 * ni2][1]),
                          "+f"(acc[mi][2 * ni2][2]), "+f"(acc[mi][2 * ni2][3])
                        : "r"(af[mi][0]), "r"(af[mi][1]),
                          "r"(af[mi][2]), "r"(af[mi][3]),
                          "r"(b00), "r"(b01));
                    asm volatile(
                        "mma.sync.aligned.m16n8k16.row.col.f32.f16.f16.f32 "
                        "{%0,%1,%2,%3}, {%4,%5,%6,%7}, {%8,%9}, {%0,%1,%2,%3};"
                        : "+f"(acc[mi][2 * ni2 + 1][0]), "+f"(acc[mi][2 * ni2 + 1][1]),
                          "+f"(acc[mi][2 * ni2 + 1][2]), "+f"(acc[mi][2 * ni2 + 1][3])
                        : "r"(af[mi][0]), "r"(af[mi][1]),
                          "r"(af[mi][2]), "r"(af[mi][3]),
                          "r"(b10), "r"(b11));
                }
            }
        }
        __syncthreads();
    }
#undef LOAD_STAGE

    // ---------------- epilogue ----------------
#pragma unroll
    for (int mi = 0; mi < 2; mi++) {
        int r0 = mBase + wm * 32 + mi * 16 + lr;
        int r1 = r0 + 8;
        float bv0 = (r0 < g.M) ? g.bias[r0] : 0.f;
        float bv1 = (r1 < g.M) ? g.bias[r1] : 0.f;
        if (g.fusePool) {
            __half* o = (__half*)g.out;
#pragma unroll
            for (int ni = 0; ni < 8; ni++) {
                int cb = nBase + wn * 64 + ni * 8 + lc * 2;
                int b2 = cb / LOUT, l2 = cb % LOUT;
                long base = (long)b2 * g.oB + (long)(l2 >> 1) * g.oL + g.mOff;
                if (r0 < g.M)
                    o[base + r0] = __float2half_rn(
                        fmaxf(fmaxf(acc[mi][ni][0], acc[mi][ni][1]) + bv0, 0.f));
                if (r1 < g.M)
                    o[base + r1] = __float2half_rn(
                        fmaxf(fmaxf(acc[mi][ni][2], acc[mi][ni][3]) + bv1, 0.f));
            }
        } else {
#pragma unroll
            for (int ni = 0; ni < 8; ni++) {
                int cb = nBase + wn * 64 + ni * 8 + lc * 2;
#pragma unroll
                for (int cc = 0; cc < 2; cc++) {
                    int n = cb + cc;
                    int b2 = n / LOUT, l2 = n % LOUT;
                    long base = (long)b2 * g.oB + (long)l2 * g.oL + g.mOff;
                    float v0 = acc[mi][ni][cc] + bv0;
                    float v1 = acc[mi][ni][2 + cc] + bv1;
                    if (g.doRelu) { v0 = fmaxf(v0, 0.f); v1 = fmaxf(v1, 0.f); }
                    if (g.outHalf) {
                        __half* o = (__half*)g.out;
                        if (r0 < g.M) o[base + r0] = __float2half_rn(v0);
                        if (r1 < g.M) o[base + r1] = __float2half_rn(v1);
                    } else {
                        float* o = (float*)g.out;
                        if (r0 < g.M) o[base + r0] = v0;
                        if (r1 < g.M) o[base + r1] = v1;
                    }
                }
            }
        }
    }
}

template<int LOUT>
__global__ __launch_bounds__(256, 2)
void gemm_one(GArgs g)
{
    extern __shared__ __half sm[];
    gemm_body<LOUT>(g, blockIdx.y * 128, blockIdx.x * 128, sm);
}

// conv1 trio in one launch: blockIdx.y selects {W5, W3, W1} (all M=100, mBase=0)
template<int LOUT>
__global__ __launch_bounds__(256, 2)
void gemm_tri(GArgs g0, GArgs g1, GArgs g2)
{
    extern __shared__ __half sm[];
    GArgs g = (blockIdx.y == 0) ? g0 : ((blockIdx.y == 1) ? g1 : g2);
    gemm_body<LOUT>(g, 0, blockIdx.x * 128, sm);
}

// max over all 50 positions
__global__ void pool3()
{
    int b = blockIdx.x;
    for (int c = threadIdx.x; c < 300; c += blockDim.x) {
        const float* src = g_O3 + (long)b * 15000 + c;
        float mx = src[0];
        for (int p = 1; p < 50; p++) mx = fmaxf(mx, src[p * 300]);
        g_H[b * 300 + c] = mx;
    }
}

// FC chain: 300 -> 100 (relu) -> 50 (relu) -> 15  (exact fp32)
__global__ void fc_chain(const float* __restrict__ d1w, const float* __restrict__ d1b,
                         const float* __restrict__ d2w, const float* __restrict__ d2b,
                         const float* __restrict__ d3w, const float* __restrict__ d3b,
                         float* __restrict__ out)
{
    __shared__ float h0[300], h1[100], h2[50];
    int b = blockIdx.x, tid = threadIdx.x;
    for (int i = tid; i < 300; i += 128) h0[i] = g_H[b * 300 + i];
    __syncthreads();
    if (tid < 100) {
        float s = d1b[tid];
        for (int k = 0; k < 300; k++) s += h0[k] * d1w[k * 100 + tid];
        h1[tid] = fmaxf(s, 0.f);
    }
    __syncthreads();
    if (tid < 50) {
        float s = d2b[tid];
        for (int k = 0; k < 100; k++) s += h1[k] * d2w[k * 50 + tid];
        h2[tid] = fmaxf(s, 0.f);
    }
    __syncthreads();
    if (tid < 15) {
        float s = d3b[tid];
        for (int k = 0; k < 50; k++) s += h2[k] * d3w[k * 15 + tid];
        out[b * 15 + tid] = s;
    }
}

extern "C" void kernel_launch(void* const* d_in, const int* in_sizes, int n_in,
                              void* d_out, int out_size)
{
    const int*   tok  = (const int*)  d_in[0];
    const int*   p1m  = (const int*)  d_in[1];
    const int*   p2m  = (const int*)  d_in[2];
    const float* sdp  = (const float*)d_in[3];
    const float* wemb = (const float*)d_in[4];
    const float* p1e  = (const float*)d_in[5];
    const float* p2e  = (const float*)d_in[6];
    const float* w11  = (const float*)d_in[7];
    const float* b11  = (const float*)d_in[8];
    const float* w13  = (const float*)d_in[9];
    const float* b13  = (const float*)d_in[10];
    const float* w15  = (const float*)d_in[11];
    const float* b15  = (const float*)d_in[12];
    const float* w2a  = (const float*)d_in[13];
    const float* b2a  = (const float*)d_in[14];
    const float* w2b  = (const float*)d_in[15];
    const float* b2b  = (const float*)d_in[16];
    const float* d1w  = (const float*)d_in[17];
    const float* d1b  = (const float*)d_in[18];
    const float* d2w  = (const float*)d_in[19];
    const float* d2b  = (const float*)d_in[20];
    const float* d3w  = (const float*)d_in[21];
    const float* d3b  = (const float*)d_in[22];

    __half *Xpad, *P, *A2, *W1, *W3, *W5, *W2a, *W2b;
    float *O3;
    cudaGetSymbolAddress((void**)&Xpad, g_Xpad);
    cudaGetSymbolAddress((void**)&P,   g_P);
    cudaGetSymbolAddress((void**)&A2,  g_A2);
    cudaGetSymbolAddress((void**)&O3,  g_O3);
    cudaGetSymbolAddress((void**)&W1,  g_W1);
    cudaGetSymbolAddress((void**)&W3,  g_W3);
    cudaGetSymbolAddress((void**)&W5,  g_W5);
    cudaGetSymbolAddress((void**)&W2a, g_W2a);
    cudaGetSymbolAddress((void**)&W2b, g_W2b);

    const int SMEM = 2 * STAGEH * 2;   // 73728 B
    cudaFuncSetAttribute(gemm_tri<100>, cudaFuncAttributeMaxDynamicSharedMemorySize, SMEM);
    cudaFuncSetAttribute(gemm_one<50>,  cudaFuncAttributeMaxDynamicSharedMemorySize, SMEM);

    prep_weights<<<dim3((100 * K5P + 255) / 256, 5), 256>>>(w11, w13, w15, w2a, w2b);

    build_x<<<BATCH * LEN, 256>>>(tok, p1m, p2m, sdp, wemb, p1e, p2e);

    long sBX = (long)XROWS * XC;

    // conv1 (x3) + relu + pool(2) fused -> P[b][p][PSTR] half, one launch
    GArgs gc5 = { W5, b15, Xpad,          P, 100, K5P, sBX, XC,
                  50L * PSTR, PSTR, 200, 1, 1, 1 };
    GArgs gc3 = { W3, b13, Xpad + XC,     P, 100, K3P, sBX, XC,
                  50L * PSTR, PSTR, 100, 1, 1, 1 };
    GArgs gc1 = { W1, b11, Xpad + 2 * XC, P, 100, K1P, sBX, XC,
                  50L * PSTR, PSTR, 0, 1, 1, 1 };
    gemm_tri<100><<<dim3(400, 3), 256, SMEM>>>(gc5, gc3, gc1);

    // conv2a (1x1) -> A2 half (padded rows 0,51 stay zero)
    GArgs g2a = { W2a, b2a, P, A2 + 200, 200, K2AP, 50L * PSTR, PSTR,
                  10400, 200, 0, 0, 1, 0 };
    gemm_one<50><<<dim3(200, 2), 256, SMEM>>>(g2a);

    // conv2b (kw=3, pad=1) + relu -> O3 float
    GArgs g2b = { W2b, b2b, A2, O3, 300, K2BP, 10400, 200,
                  15000, 300, 0, 1, 0, 0 };
    gemm_one<50><<<dim3(200, 3), 256, SMEM>>>(g2b);

    pool3<<<BATCH, 256>>>();

    fc_chain<<<BATCH, 128>>>(d1w, d1b, d2w, d2b, d3w, d3b, (float*)d_out);
}

// round 7
// speedup vs baseline: 2.6377x; 1.0906x over previous
#include <cuda_runtime.h>
#include <cuda_fp16.h>

// ---------------------------------------------------------------------------
// Net_25469156065564: PCNN forward. fp16 mma.sync m16n8k16 (fp32 accum),
// ldmatrix feed, 3-stage cp.async (single barrier/chunk), conv1 trio fused,
// relu+maxpool(2) in conv1 epilogue, pool3 fused into FC kernel.
// ---------------------------------------------------------------------------

#define BATCH 512
#define LEN   100
#define XROWS 104
#define XC    752          // 750 data + 2 pad halves (16B row stride)

#define K1P  768
#define K3P  2304
#define K5P  3776
#define K2AP 320
#define K2BP 640

#define PSTR 304           // P row stride (halves)

__device__ __align__(16) __half g_Xpad[BATCH * XROWS * XC + 128];
__device__ __align__(16) __half g_P [BATCH * 50 * PSTR + 128];
__device__ __align__(16) __half g_A2[BATCH * 52 * 200 + 128];
__device__ __align__(16) float  g_O3[BATCH * 50 * 300];
__device__ __align__(16) __half g_W1 [128 * K1P];
__device__ __align__(16) __half g_W3 [128 * K3P];
__device__ __align__(16) __half g_W5 [128 * K5P];
__device__ __align__(16) __half g_W2a[256 * K2AP];
__device__ __align__(16) __half g_W2b[384 * K2BP];

// ---------------------------------------------------------------------------
__global__ void prep_weights(const float* __restrict__ w11,
                             const float* __restrict__ w13,
                             const float* __restrict__ w15,
                             const float* __restrict__ w2a,
                             const float* __restrict__ w2b)
{
    int which = blockIdx.y;
    int idx = blockIdx.x * 256 + threadIdx.x;
    if (which == 0) {                       // w11 (100,250,3,1) -> [100][768]
        if (idx >= 100 * K1P) return;
        int o = idx / K1P, k = idx % K1P;
        float v = 0.f;
        if (k < 750) { int h = k / 250, ci = k % 250; v = w11[o * 750 + ci * 3 + h]; }
        g_W1[idx] = __float2half_rn(v);
    } else if (which == 1) {                // w13 (100,250,3,3) -> [100][2304]
        if (idx >= 100 * K3P) return;
        int o = idx / K3P, k = idx % K3P;
        float v = 0.f;
        if (k < 2256) {
            int kw = k / 752, r = k % 752;
            if (r < 750) { int h = r / 250, ci = r % 250; v = w13[o * 2250 + ci * 9 + h * 3 + kw]; }
        }
        g_W3[idx] = __float2half_rn(v);
    } else if (which == 2) {                // w15 (100,250,3,5) -> [100][3776]
        if (idx >= 100 * K5P) return;
        int o = idx / K5P, k = idx % K5P;
        float v = 0.f;
        if (k < 3760) {
            int kw = k / 752, r = k % 752;
            if (r < 750) { int h = r / 250, ci = r % 250; v = w15[o * 3750 + ci * 15 + h * 5 + kw]; }
        }
        g_W5[idx] = __float2half_rn(v);
    } else if (which == 3) {                // w2b (300,200,1,3) -> [300][640]
        if (idx >= 300 * K2BP) return;
        int o = idx / K2BP, k = idx % K2BP;
        float v = 0.f;
        if (k < 600) { int kw = k / 200, c2 = k % 200; v = w2b[o * 600 + c2 * 3 + kw]; }
        g_W2b[idx] = __float2half_rn(v);
    } else {                                // w2a (200,300,1,1) -> [200][320]
        if (idx >= 200 * K2AP) return;
        int o = idx / K2AP, k = idx % K2AP;
        g_W2a[idx] = __float2half_rn((k < 300) ? w2a[o * 300 + k] : 0.f);
    }
}

// ---------------------------------------------------------------------------
// Build Xpad rows 2..101; half2 vectorized (125 lanes do 2 elems per region).
__global__ void build_x(const int* __restrict__ tok,
                        const int* __restrict__ p1m,
                        const int* __restrict__ p2m,
                        const float* __restrict__ sdp,
                        const float* __restrict__ wemb,
                        const float* __restrict__ p1e,
                        const float* __restrict__ p2e)
{
    int blk = blockIdx.x;
    int b = blk / LEN, l = blk % LEN;
    int tid = threadIdx.x;
    if (tid >= 125) return;
    int t  = tok[b * LEN + l];
    int p1 = p1m[b * LEN + l];
    int p2 = p2m[b * LEN + l];
    float s = sdp[b * LEN + l];
    __half2* row2 = (__half2*)(g_Xpad + ((long)(b * XROWS + l + 2)) * XC);

    float2 w = *(const float2*)(wemb + (long)t * 250 + 2 * tid);
    row2[tid] = __floats2half2_rn(w.x, w.y);
    row2[250 + tid] = __floats2half2_rn(s * w.x, s * w.y);

    int c0 = 250 + 2 * tid, c1 = c0 + 1;
    float v0 = (c0 < 375) ? p1e[p1 * 125 + (c0 - 250)] : p2e[p2 * 125 + (c0 - 375)];
    float v1 = (c1 < 375) ? p1e[p1 * 125 + (c1 - 250)] : p2e[p2 * 125 + (c1 - 375)];
    row2[125 + tid] = __floats2half2_rn(v0, v1);
}

// ---------------------------------------------------------------------------
// GEMM body. CTA 128x128, BK=64 halves, 8 warps (4M x 2N), warp 32x64.
// 3-stage cp.async, single __syncthreads per chunk, ldmatrix + m16n8k16.
// ---------------------------------------------------------------------------
#define TILEH 9216     // halves per A or B tile (128*72)
#define STAGEH 18432   // halves per stage (A+B)

struct GArgs {
    const __half* W; const float* bias; const __half* X; void* out;
    int M, Kp; long sB; int sL; long oB; int oL;
    int mOff, doRelu, outHalf, fusePool;
};

template<int LOUT>
__device__ __forceinline__ void gemm_body(const GArgs g, int mBase, int nBase,
                                          __half* sm)
{
    const __half* __restrict__ W = g.W;
    const __half* __restrict__ X = g.X;

    int tid = threadIdx.x;
    int lane = tid & 31;
    int warp = tid >> 5;
    int wm = warp & 3;
    int wn = warp >> 2;
    int lr = lane >> 2;
    int lc = lane & 3;

    // cp.async mapping: both tiles 128 rows x 64 halves, 16B chunks.
    int cj = (tid & 7) * 8, cr = tid >> 3;
    int aOff[4];
    long bOff[4];
    unsigned aDst[4], bDst[4];
#pragma unroll
    for (int i = 0; i < 4; i++) {
        int row = cr + 32 * i;
        aOff[i] = (mBase + row) * g.Kp + cj;
        aDst[i] = (unsigned)__cvta_generic_to_shared(sm + row * 72 + cj);
        int n = nBase + row;
        int bb = n / LOUT, ll = n % LOUT;
        bOff[i] = (long)bb * g.sB + (long)ll * g.sL + cj;
        bDst[i] = (unsigned)__cvta_generic_to_shared(sm + TILEH + row * 72 + cj);
    }

    // ldmatrix base addresses (stage 0)
    unsigned aLm[2], bLm[4];
    {
        int arow = (lane & 15);
        int akhi = (lane >> 4) * 8;
#pragma unroll
        for (int mi = 0; mi < 2; mi++) {
            int row = wm * 32 + mi * 16 + arow;
            aLm[mi] = (unsigned)__cvta_generic_to_shared(sm + row * 72 + akhi);
        }
        int bcol = ((lane >> 4) << 3) + (lane & 7);
        int bkhi = ((lane >> 3) & 1) * 8;
#pragma unroll
        for (int ni2 = 0; ni2 < 4; ni2++) {
            int col = wn * 64 + ni2 * 16 + bcol;
            bLm[ni2] = (unsigned)__cvta_generic_to_shared(sm + TILEH + col * 72 + bkhi);
        }
    }

    float acc[2][8][4];
#pragma unroll
    for (int i = 0; i < 2; i++)
#pragma unroll
        for (int j = 0; j < 8; j++)
#pragma unroll
            for (int q = 0; q < 4; q++) acc[i][j][q] = 0.f;

    int nCh = g.Kp >> 6;                 // >= 5 for all our GEMMs
    const unsigned stageB = (unsigned)STAGEH * 2u;

#define LOAD_STAGE(ko_, so_)                                                    \
    do {                                                                        \
        _Pragma("unroll")                                                       \
        for (int i_ = 0; i_ < 4; i_++) {                                        \
            asm volatile("cp.async.cg.shared.global [%0],[%1],16;"              \
                         :: "r"(aDst[i_] + (so_)), "l"(W + aOff[i_] + (ko_)));  \
            asm volatile("cp.async.cg.shared.global [%0],[%1],16;"              \
                         :: "r"(bDst[i_] + (so_)), "l"(X + bOff[i_] + (ko_)));  \
        }                                                                       \
    } while (0)

    // prologue: stages 0,1
    LOAD_STAGE(0, 0u);
    asm volatile("cp.async.commit_group;");
    LOAD_STAGE(64, stageB);
    asm volatile("cp.async.commit_group;");

    unsigned so = 0;                      // read-stage byte offset
    for (int c = 0; c < nCh; c++) {
        if (c + 1 < nCh) asm volatile("cp.async.wait_group 1;");
        else             asm volatile("cp.async.wait_group 0;");
        __syncthreads();

        if (c + 2 < nCh) {
            unsigned wrSo = so + 2u * stageB;
            if (wrSo >= 3u * stageB) wrSo -= 3u * stageB;
            LOAD_STAGE((c + 2) * 64, wrSo);
            asm volatile("cp.async.commit_group;");
        }

#pragma unroll
        for (int kk = 0; kk < 4; kk++) {
            unsigned ko = so + kk * 32;   // 16 halves = 32 bytes
            unsigned af[2][4];
#pragma unroll
            for (int mi = 0; mi < 2; mi++)
                asm volatile("ldmatrix.sync.aligned.m8n8.x4.shared.b16 "
                             "{%0,%1,%2,%3}, [%4];"
                             : "=r"(af[mi][0]), "=r"(af[mi][1]),
                               "=r"(af[mi][2]), "=r"(af[mi][3])
                             : "r"(aLm[mi] + ko));
#pragma unroll
            for (int ni2 = 0; ni2 < 4; ni2++) {
                unsigned b00, b01, b10, b11;
                asm volatile("ldmatrix.sync.aligned.m8n8.x4.shared.b16 "
                             "{%0,%1,%2,%3}, [%4];"
                             : "=r"(b00), "=r"(b01), "=r"(b10), "=r"(b11)
                             : "r"(bLm[ni2] + ko));
#pragma unroll
                for (int mi = 0; mi < 2; mi++) {
                    asm volatile(
                        "mma.sync.aligned.m16n8k16.row.col.f32.f16.f16.f32 "
                        "{%0,%1,%2,%3}, {%4,%5,%6,%7}, {%8,%9}, {%0,%1,%2,%3};"
                        : "+f"(acc[mi][2 * ni2][0]), "+f"(acc[mi][2 * ni2][1]),
                          "+f"(acc[mi][2 * ni2][2]), "+f"(acc[mi][2 * ni2][3])
                        : "r"(af[mi][0]), "r"(af[mi][1]),
                          "r"(af[mi][2]), "r"(af[mi][3]),
                          "r"(b00), "r"(b01));
                    asm volatile(
                        "mma.sync.aligned.m16n8k16.row.col.f32.f16.f16.f32 "
                        "{%0,%1,%2,%3}, {%4,%5,%6,%7}, {%8,%9}, {%0,%1,%2,%3};"
                        : "+f"(acc[mi][2 * ni2 + 1][0]), "+f"(acc[mi][2 * ni2 + 1][1]),
                          "+f"(acc[mi][2 * ni2 + 1][2]), "+f"(acc[mi][2 * ni2 + 1][3])
                        : "r"(af[mi][0]), "r"(af[mi][1]),
                          "r"(af[mi][2]), "r"(af[mi][3]),
                          "r"(b10), "r"(b11));
                }
            }
        }
        so += stageB;
        if (so == 3u * stageB) so = 0;
    }
#undef LOAD_STAGE

    // ---------------- epilogue ----------------
#pragma unroll
    for (int mi = 0; mi < 2; mi++) {
        int r0 = mBase + wm * 32 + mi * 16 + lr;
        int r1 = r0 + 8;
        float bv0 = (r0 < g.M) ? g.bias[r0] : 0.f;
        float bv1 = (r1 < g.M) ? g.bias[r1] : 0.f;
        if (g.fusePool) {
            __half* o = (__half*)g.out;
#pragma unroll
            for (int ni = 0; ni < 8; ni++) {
                int cb = nBase + wn * 64 + ni * 8 + lc * 2;
                int b2 = cb / LOUT, l2 = cb % LOUT;
                long base = (long)b2 * g.oB + (long)(l2 >> 1) * g.oL + g.mOff;
                if (r0 < g.M)
                    o[base + r0] = __float2half_rn(
                        fmaxf(fmaxf(acc[mi][ni][0], acc[mi][ni][1]) + bv0, 0.f));
                if (r1 < g.M)
                    o[base + r1] = __float2half_rn(
                        fmaxf(fmaxf(acc[mi][ni][2], acc[mi][ni][3]) + bv1, 0.f));
            }
        } else {
#pragma unroll
            for (int ni = 0; ni < 8; ni++) {
                int cb = nBase + wn * 64 + ni * 8 + lc * 2;
#pragma unroll
                for (int cc = 0; cc < 2; cc++) {
                    int n = cb + cc;
                    int b2 = n / LOUT, l2 = n % LOUT;
                    long base = (long)b2 * g.oB + (long)l2 * g.oL + g.mOff;
                    float v0 = acc[mi][ni][cc] + bv0;
                    float v1 = acc[mi][ni][2 + cc] + bv1;
                    if (g.doRelu) { v0 = fmaxf(v0, 0.f); v1 = fmaxf(v1, 0.f); }
                    if (g.outHalf) {
                        __half* o = (__half*)g.out;
                        if (r0 < g.M) o[base + r0] = __float2half_rn(v0);
                        if (r1 < g.M) o[base + r1] = __float2half_rn(v1);
                    } else {
                        float* o = (float*)g.out;
                        if (r0 < g.M) o[base + r0] = v0;
                        if (r1 < g.M) o[base + r1] = v1;
                    }
                }
            }
        }
    }
}

template<int LOUT>
__global__ __launch_bounds__(256, 2)
void gemm_one(GArgs g)
{
    extern __shared__ __half sm[];
    gemm_body<LOUT>(g, blockIdx.y * 128, blockIdx.x * 128, sm);
}

template<int LOUT>
__global__ __launch_bounds__(256, 2)
void gemm_tri(GArgs g0, GArgs g1, GArgs g2)
{
    extern __shared__ __half sm[];
    GArgs g = (blockIdx.y == 0) ? g0 : ((blockIdx.y == 1) ? g1 : g2);
    gemm_body<LOUT>(g, 0, blockIdx.x * 128, sm);
}

// pool over 50 positions + FC chain 300 -> 100 -> 50 -> 15 (fp32)
__global__ void pool_fc(const float* __restrict__ d1w, const float* __restrict__ d1b,
                        const float* __restrict__ d2w, const float* __restrict__ d2b,
                        const float* __restrict__ d3w, const float* __restrict__ d3b,
                        float* __restrict__ out)
{
    __shared__ float h0[300], h1[100], h2[50];
    int b = blockIdx.x, tid = threadIdx.x;
    for (int c = tid; c < 300; c += 128) {
        const float* src = g_O3 + (long)b * 15000 + c;
        float mx = src[0];
        for (int p = 1; p < 50; p++) mx = fmaxf(mx, src[p * 300]);
        h0[c] = mx;
    }
    __syncthreads();
    if (tid < 100) {
        float s = d1b[tid];
        for (int k = 0; k < 300; k++) s += h0[k] * d1w[k * 100 + tid];
        h1[tid] = fmaxf(s, 0.f);
    }
    __syncthreads();
    if (tid < 50) {
        float s = d2b[tid];
        for (int k = 0; k < 100; k++) s += h1[k] * d2w[k * 50 + tid];
        h2[tid] = fmaxf(s, 0.f);
    }
    __syncthreads();
    if (tid < 15) {
        float s = d3b[tid];
        for (int k = 0; k < 50; k++) s += h2[k] * d3w[k * 15 + tid];
        out[b * 15 + tid] = s;
    }
}

extern "C" void kernel_launch(void* const* d_in, const int* in_sizes, int n_in,
                              void* d_out, int out_size)
{
    const int*   tok  = (const int*)  d_in[0];
    const int*   p1m  = (const int*)  d_in[1];
    const int*   p2m  = (const int*)  d_in[2];
    const float* sdp  = (const float*)d_in[3];
    const float* wemb = (const float*)d_in[4];
    const float* p1e  = (const float*)d_in[5];
    const float* p2e  = (const float*)d_in[6];
    const float* w11  = (const float*)d_in[7];
    const float* b11  = (const float*)d_in[8];
    const float* w13  = (const float*)d_in[9];
    const float* b13  = (const float*)d_in[10];
    const float* w15  = (const float*)d_in[11];
    const float* b15  = (const float*)d_in[12];
    const float* w2a  = (const float*)d_in[13];
    const float* b2a  = (const float*)d_in[14];
    const float* w2b  = (const float*)d_in[15];
    const float* b2b  = (const float*)d_in[16];
    const float* d1w  = (const float*)d_in[17];
    const float* d1b  = (const float*)d_in[18];
    const float* d2w  = (const float*)d_in[19];
    const float* d2b  = (const float*)d_in[20];
    const float* d3w  = (const float*)d_in[21];
    const float* d3b  = (const float*)d_in[22];

    __half *Xpad, *P, *A2, *W1, *W3, *W5, *W2a, *W2b;
    float *O3;
    cudaGetSymbolAddress((void**)&Xpad, g_Xpad);
    cudaGetSymbolAddress((void**)&P,   g_P);
    cudaGetSymbolAddress((void**)&A2,  g_A2);
    cudaGetSymbolAddress((void**)&O3,  g_O3);
    cudaGetSymbolAddress((void**)&W1,  g_W1);
    cudaGetSymbolAddress((void**)&W3,  g_W3);
    cudaGetSymbolAddress((void**)&W5,  g_W5);
    cudaGetSymbolAddress((void**)&W2a, g_W2a);
    cudaGetSymbolAddress((void**)&W2b, g_W2b);

    const int SMEM = 3 * STAGEH * 2;   // 110592 B (3 stages)
    cudaFuncSetAttribute(gemm_tri<100>, cudaFuncAttributeMaxDynamicSharedMemorySize, SMEM);
    cudaFuncSetAttribute(gemm_one<50>,  cudaFuncAttributeMaxDynamicSharedMemorySize, SMEM);

    prep_weights<<<dim3((100 * K5P + 255) / 256, 5), 256>>>(w11, w13, w15, w2a, w2b);

    build_x<<<BATCH * LEN, 128>>>(tok, p1m, p2m, sdp, wemb, p1e, p2e);

    long sBX = (long)XROWS * XC;

    // conv1 (x3) + relu + pool(2) fused -> P[b][p][PSTR] half, one launch
    GArgs gc5 = { W5, b15, Xpad,          P, 100, K5P, sBX, XC,
                  50L * PSTR, PSTR, 200, 1, 1, 1 };
    GArgs gc3 = { W3, b13, Xpad + XC,     P, 100, K3P, sBX, XC,
                  50L * PSTR, PSTR, 100, 1, 1, 1 };
    GArgs gc1 = { W1, b11, Xpad + 2 * XC, P, 100, K1P, sBX, XC,
                  50L * PSTR, PSTR, 0, 1, 1, 1 };
    gemm_tri<100><<<dim3(400, 3), 256, SMEM>>>(gc5, gc3, gc1);

    // conv2a (1x1) -> A2 half (padded rows 0,51 stay zero)
    GArgs g2a = { W2a, b2a, P, A2 + 200, 200, K2AP, 50L * PSTR, PSTR,
                  10400, 200, 0, 0, 1, 0 };
    gemm_one<50><<<dim3(200, 2), 256, SMEM>>>(g2a);

    // conv2b (kw=3, pad=1) + relu -> O3 float
    GArgs g2b = { W2b, b2b, A2, O3, 300, K2BP, 10400, 200,
                  15000, 300, 0, 1, 0, 0 };
    gemm_one<50><<<dim3(200, 3), 256, SMEM>>>(g2b);

    pool_fc<<<BATCH, 128>>>(d1w, d1b, d2w, d2b, d3w, d3b, (float*)d_out);
}